// round 1
// baseline (speedup 1.0000x reference)
#include <cuda_runtime.h>
#include <math.h>

// Problem constants
#define B_    2
#define S_    2048
#define DIM_  1024
#define H_    16
#define HD_   64
#define FFN_  4096
#define NTOK  (B_*S_)   // 4096

// ---------------------------------------------------------------------------
// Scratch (static device globals — no allocation in kernel_launch)
// ---------------------------------------------------------------------------
__device__ float g_h1 [NTOK*DIM_];      // LN output (reused for LN1 and LN2)
__device__ float g_qkv[NTOK*3*DIM_];    // qkv projection
__device__ float g_q  [NTOK*DIM_];      // [B,H,S,HD] after rope
__device__ float g_k  [NTOK*DIM_];
__device__ float g_v  [NTOK*DIM_];
__device__ float g_ctx[NTOK*DIM_];      // attention output [B,S,DIM]
__device__ float g_x1 [NTOK*DIM_];      // residual after attention
__device__ float g_mid[NTOK*FFN_];      // FFN intermediate

// ---------------------------------------------------------------------------
// LayerNorm: one block per row (1024 cols, 256 threads, float4 per thread)
// ---------------------------------------------------------------------------
__global__ void __launch_bounds__(256) ln_kernel(
    const float* __restrict__ x, const float* __restrict__ gw,
    const float* __restrict__ bw, float* __restrict__ y)
{
    int row = blockIdx.x;
    int tid = threadIdx.x;
    float4 v = ((const float4*)(x + (size_t)row*DIM_))[tid];
    float s  = v.x + v.y + v.z + v.w;
    float ss = v.x*v.x + v.y*v.y + v.z*v.z + v.w*v.w;
    #pragma unroll
    for (int o = 16; o; o >>= 1) {
        s  += __shfl_xor_sync(0xffffffffu, s,  o);
        ss += __shfl_xor_sync(0xffffffffu, ss, o);
    }
    __shared__ float sm1[8], sm2[8];
    int w = tid >> 5;
    if ((tid & 31) == 0) { sm1[w] = s; sm2[w] = ss; }
    __syncthreads();
    s = 0.f; ss = 0.f;
    #pragma unroll
    for (int i = 0; i < 8; i++) { s += sm1[i]; ss += sm2[i]; }
    float mu  = s * (1.0f/1024.0f);
    float var = ss * (1.0f/1024.0f) - mu*mu;
    float r   = rsqrtf(var + 1e-5f);
    float4 g4 = ((const float4*)gw)[tid];
    float4 b4 = ((const float4*)bw)[tid];
    float4 o;
    o.x = (v.x - mu)*r*g4.x + b4.x;
    o.y = (v.y - mu)*r*g4.y + b4.y;
    o.z = (v.z - mu)*r*g4.z + b4.z;
    o.w = (v.w - mu)*r*g4.w + b4.w;
    ((float4*)(y + (size_t)row*DIM_))[tid] = o;
}

// ---------------------------------------------------------------------------
// SGEMM: C[M,N] = A[M,K] @ B[K,N] + bias (+ GELU) (+ residual)
// 128x128 block tile, BK=8, 256 threads, 8x8 per thread (split 4+4 frags)
// ACT: 0 = none, 1 = exact GELU.  RES: add res[M,N].
// ---------------------------------------------------------------------------
template<int ACT, bool RES>
__global__ void __launch_bounds__(256) sgemm_kernel(
    const float* __restrict__ A, const float* __restrict__ Bm,
    const float* __restrict__ bias, const float* __restrict__ res,
    float* __restrict__ C, int M, int N, int K)
{
    __shared__ float As[8][128];
    __shared__ float Bs[8][128];
    int tid = threadIdx.x;
    int bx = blockIdx.x, by = blockIdx.y;
    const float* Ab = A  + (size_t)by*128*K;
    const float* Bb = Bm + (size_t)bx*128;
    int arow = tid >> 1, acol = (tid & 1) << 2;
    int brow = tid >> 5, bcol = (tid & 31) << 2;
    int tx = tid & 15, ty = tid >> 4;

    float acc[8][8];
    #pragma unroll
    for (int i = 0; i < 8; i++)
        #pragma unroll
        for (int j = 0; j < 8; j++) acc[i][j] = 0.f;

    for (int k0 = 0; k0 < K; k0 += 8) {
        float4 av = *(const float4*)(Ab + (size_t)arow*K + k0 + acol);
        As[acol+0][arow] = av.x;
        As[acol+1][arow] = av.y;
        As[acol+2][arow] = av.z;
        As[acol+3][arow] = av.w;
        *(float4*)&Bs[brow][bcol] = *(const float4*)(Bb + (size_t)(k0+brow)*N + bcol);
        __syncthreads();
        #pragma unroll
        for (int kk = 0; kk < 8; kk++) {
            float a[8], b[8];
            *(float4*)(a)   = *(float4*)&As[kk][ty*4];
            *(float4*)(a+4) = *(float4*)&As[kk][64 + ty*4];
            *(float4*)(b)   = *(float4*)&Bs[kk][tx*4];
            *(float4*)(b+4) = *(float4*)&Bs[kk][64 + tx*4];
            #pragma unroll
            for (int i = 0; i < 8; i++)
                #pragma unroll
                for (int j = 0; j < 8; j++)
                    acc[i][j] = fmaf(a[i], b[j], acc[i][j]);
        }
        __syncthreads();
    }

    #pragma unroll
    for (int i = 0; i < 8; i++) {
        int r = by*128 + ((i < 4) ? (ty*4 + i) : (64 + ty*4 + (i-4)));
        #pragma unroll
        for (int jh = 0; jh < 2; jh++) {
            int c = bx*128 + jh*64 + tx*4;
            float vv[4];
            #pragma unroll
            for (int j = 0; j < 4; j++) {
                float v = acc[i][jh*4 + j] + bias[c + j];
                if (ACT == 1)
                    v = 0.5f * v * (1.0f + erff(v * 0.70710678118654752f));
                if (RES)
                    v += res[(size_t)r*N + c + j];
                vv[j] = v;
            }
            *(float4*)(&C[(size_t)r*N + c]) = make_float4(vv[0], vv[1], vv[2], vv[3]);
        }
    }
}

// ---------------------------------------------------------------------------
// RoPE + QKV split/reshape: qkv [NTOK, 3*DIM] -> Q/K/V [B,H,S,HD] (rotated)
// One thread per (b,s,h,d<32) pair handles (d, d+32).
// ---------------------------------------------------------------------------
__global__ void __launch_bounds__(256) rope_kernel(
    const float* __restrict__ qkv,
    float* __restrict__ Q, float* __restrict__ K, float* __restrict__ V)
{
    int idx = blockIdx.x * blockDim.x + threadIdx.x;   // 2^21 total
    int d = idx & 31;
    int h = (idx >> 5) & 15;
    int s = (idx >> 9) & 2047;
    int b = idx >> 20;
    int t = b*S_ + s;
    size_t base = (size_t)t*3072 + h*64 + d;
    float q1 = qkv[base],        q2 = qkv[base + 32];
    float k1 = qkv[base + 1024], k2 = qkv[base + 1056];
    float v1 = qkv[base + 2048], v2 = qkv[base + 2080];
    float inv = powf(10000.0f, -(float)d * (1.0f/32.0f));
    float ang = (float)s * inv;
    float sn, cs;
    sincosf(ang, &sn, &cs);
    size_t o = ((size_t)(b*H_ + h)*S_ + s)*64 + d;
    Q[o]      = q1*cs - q2*sn;
    Q[o + 32] = q2*cs + q1*sn;
    K[o]      = k1*cs - k2*sn;
    K[o + 32] = k2*cs + k1*sn;
    V[o]      = v1;
    V[o + 32] = v2;
}

// ---------------------------------------------------------------------------
// Flash attention, fp32: 64x64 q/k tiles, HD=64, online softmax.
// 256 threads = 16(tx: j/d cols) x 16(ty: i rows), 4x4 frags, float4 dot4.
// K tile stored with XOR swizzle on 16B groups to kill bank conflicts.
// ---------------------------------------------------------------------------
__global__ void __launch_bounds__(256) attn_kernel(
    const float* __restrict__ Q, const float* __restrict__ K,
    const float* __restrict__ V, const unsigned char* __restrict__ mask,
    float* __restrict__ O)
{
    extern __shared__ float sm[];
    float* q_s = sm;             // [64][64]
    float* k_s = sm + 4096;     // [64][64] swizzled
    float* v_s = sm + 8192;     // [64][64]
    float* p_s = sm + 12288;    // [64][64]
    float* mk  = sm + 16384;    // [64]

    int tid = threadIdx.x;
    int tx = tid & 15, ty = tid >> 4;
    int bh = blockIdx.y;
    int b  = bh >> 4, h = bh & 15;
    int qt = blockIdx.x;
    const float* Qb = Q + ((size_t)bh*S_ + (size_t)qt*64)*64;
    const float* Kb = K + (size_t)bh*S_*64;
    const float* Vb = V + (size_t)bh*S_*64;

    // load q tile (row-major [i][d])
    {
        int i0 = tid >> 4;
        int d4 = (tid & 15) << 2;
        #pragma unroll
        for (int rep = 0; rep < 4; rep++) {
            int i = i0 + rep*16;
            *(float4*)&q_s[i*64 + d4] = *(const float4*)&Qb[(size_t)i*64 + d4];
        }
    }

    float m[4], l[4], acc[4][4];
    #pragma unroll
    for (int i = 0; i < 4; i++) {
        m[i] = -3.0e38f; l[i] = 0.f;
        #pragma unroll
        for (int j = 0; j < 4; j++) acc[i][j] = 0.f;
    }

    int xo = tx & 7;
    for (int kt = 0; kt < 32; kt++) {
        __syncthreads();   // protect k_s/v_s from previous iteration's readers
        {
            int j0 = tid >> 4;
            int g  = tid & 15;
            #pragma unroll
            for (int rep = 0; rep < 4; rep++) {
                int j = j0 + rep*16;
                float4 kv = *(const float4*)&Kb[((size_t)kt*64 + j)*64 + g*4];
                int gp = g ^ ((j >> 2) & 7);
                *(float4*)&k_s[j*64 + gp*4] = kv;
                *(float4*)&v_s[j*64 + g*4]  = *(const float4*)&Vb[((size_t)kt*64 + j)*64 + g*4];
            }
            if (tid < 64)
                mk[tid] = mask[(size_t)b*S_ + kt*64 + tid] ? -3.0e38f : 0.0f;
        }
        __syncthreads();

        // scores: S[i][j] = q[i,:] . k[j,:]
        float sc[4][4];
        #pragma unroll
        for (int i = 0; i < 4; i++)
            #pragma unroll
            for (int j = 0; j < 4; j++) sc[i][j] = 0.f;
        #pragma unroll
        for (int g = 0; g < 16; g++) {
            float4 qv[4], kv[4];
            #pragma unroll
            for (int i = 0; i < 4; i++)
                qv[i] = *(float4*)&q_s[(ty*4 + i)*64 + g*4];
            int gp = (g ^ xo) * 4;
            #pragma unroll
            for (int j = 0; j < 4; j++)
                kv[j] = *(float4*)&k_s[(tx*4 + j)*64 + gp];
            #pragma unroll
            for (int i = 0; i < 4; i++)
                #pragma unroll
                for (int j = 0; j < 4; j++)
                    sc[i][j] += qv[i].x*kv[j].x + qv[i].y*kv[j].y
                              + qv[i].z*kv[j].z + qv[i].w*kv[j].w;
        }

        // scale + mask + online softmax update
        #pragma unroll
        for (int i = 0; i < 4; i++) {
            float rmax = -3.0e38f;
            #pragma unroll
            for (int j = 0; j < 4; j++) {
                sc[i][j] = sc[i][j]*0.125f + mk[tx*4 + j];
                rmax = fmaxf(rmax, sc[i][j]);
            }
            #pragma unroll
            for (int o = 8; o >= 1; o >>= 1)
                rmax = fmaxf(rmax, __shfl_xor_sync(0xffffffffu, rmax, o, 16));
            float mn   = fmaxf(m[i], rmax);
            float corr = __expf(m[i] - mn);
            float p[4];
            float rsum = 0.f;
            #pragma unroll
            for (int j = 0; j < 4; j++) { p[j] = expf(sc[i][j] - mn); rsum += p[j]; }
            #pragma unroll
            for (int o = 8; o >= 1; o >>= 1)
                rsum += __shfl_xor_sync(0xffffffffu, rsum, o, 16);
            m[i] = mn;
            l[i] = l[i]*corr + rsum;
            #pragma unroll
            for (int j = 0; j < 4; j++) acc[i][j] *= corr;
            *(float4*)&p_s[(ty*4 + i)*64 + tx*4] = make_float4(p[0], p[1], p[2], p[3]);
        }
        __syncthreads();

        // acc += P @ V
        #pragma unroll
        for (int j4 = 0; j4 < 16; j4++) {
            float4 pv[4], vv[4];
            #pragma unroll
            for (int i = 0; i < 4; i++)
                pv[i] = *(float4*)&p_s[(ty*4 + i)*64 + j4*4];
            #pragma unroll
            for (int j = 0; j < 4; j++)
                vv[j] = *(float4*)&v_s[(j4*4 + j)*64 + tx*4];
            #pragma unroll
            for (int i = 0; i < 4; i++) {
                acc[i][0] += pv[i].x*vv[0].x + pv[i].y*vv[1].x + pv[i].z*vv[2].x + pv[i].w*vv[3].x;
                acc[i][1] += pv[i].x*vv[0].y + pv[i].y*vv[1].y + pv[i].z*vv[2].y + pv[i].w*vv[3].y;
                acc[i][2] += pv[i].x*vv[0].z + pv[i].y*vv[1].z + pv[i].z*vv[2].z + pv[i].w*vv[3].z;
                acc[i][3] += pv[i].x*vv[0].w + pv[i].y*vv[1].w + pv[i].z*vv[2].w + pv[i].w*vv[3].w;
            }
        }
    }

    // final normalize + write ctx as [B, S, DIM] (heads interleaved)
    #pragma unroll
    for (int i = 0; i < 4; i++) {
        float inv = 1.0f / l[i];
        int row = qt*64 + ty*4 + i;
        size_t o = ((size_t)b*S_ + row)*DIM_ + h*64 + tx*4;
        *(float4*)&O[o] = make_float4(acc[i][0]*inv, acc[i][1]*inv,
                                      acc[i][2]*inv, acc[i][3]*inv);
    }
}

// ---------------------------------------------------------------------------
// Orchestration
// ---------------------------------------------------------------------------
extern "C" void kernel_launch(void* const* d_in, const int* in_sizes, int n_in,
                              void* d_out, int out_size)
{
    (void)in_sizes; (void)n_in; (void)out_size;
    const float*         x     = (const float*)d_in[0];
    const unsigned char* mask  = (const unsigned char*)d_in[1];
    const float*         qkv_w = (const float*)d_in[2];
    const float*         qkv_b = (const float*)d_in[3];
    const float*         out_w = (const float*)d_in[4];
    const float*         out_b = (const float*)d_in[5];
    const float*         ln1_g = (const float*)d_in[6];
    const float*         ln1_b = (const float*)d_in[7];
    const float*         ln2_g = (const float*)d_in[8];
    const float*         ln2_b = (const float*)d_in[9];
    const float*         w1    = (const float*)d_in[10];
    const float*         b1    = (const float*)d_in[11];
    const float*         w2    = (const float*)d_in[12];
    const float*         b2    = (const float*)d_in[13];
    float* out = (float*)d_out;

    float *h1, *qkv, *q, *k, *v, *ctx, *x1, *mid;
    cudaGetSymbolAddress((void**)&h1,  g_h1);
    cudaGetSymbolAddress((void**)&qkv, g_qkv);
    cudaGetSymbolAddress((void**)&q,   g_q);
    cudaGetSymbolAddress((void**)&k,   g_k);
    cudaGetSymbolAddress((void**)&v,   g_v);
    cudaGetSymbolAddress((void**)&ctx, g_ctx);
    cudaGetSymbolAddress((void**)&x1,  g_x1);
    cudaGetSymbolAddress((void**)&mid, g_mid);

    const int ATTN_SMEM = (4*64*64 + 64) * (int)sizeof(float);  // 65792
    cudaFuncSetAttribute(attn_kernel, cudaFuncAttributeMaxDynamicSharedMemorySize,
                         ATTN_SMEM);

    // 1. LN1
    ln_kernel<<<NTOK, 256>>>(x, ln1_g, ln1_b, h1);
    // 2. QKV = LN1 @ qkv_w + qkv_b
    sgemm_kernel<0, false><<<dim3(3*DIM_/128, NTOK/128), 256>>>(
        h1, qkv_w, qkv_b, nullptr, qkv, NTOK, 3*DIM_, DIM_);
    // 3. RoPE + reshape
    rope_kernel<<<(NTOK*H_*32)/256, 256>>>(qkv, q, k, v);
    // 4. Attention
    attn_kernel<<<dim3(S_/64, B_*H_), 256, ATTN_SMEM>>>(q, k, v, mask, ctx);
    // 5. x1 = x + ctx @ out_w + out_b
    sgemm_kernel<0, true><<<dim3(DIM_/128, NTOK/128), 256>>>(
        ctx, out_w, out_b, x, x1, NTOK, DIM_, DIM_);
    // 6. LN2
    ln_kernel<<<NTOK, 256>>>(x1, ln2_g, ln2_b, h1);
    // 7. mid = gelu(LN2 @ w1 + b1)
    sgemm_kernel<1, false><<<dim3(FFN_/128, NTOK/128), 256>>>(
        h1, w1, b1, nullptr, mid, NTOK, FFN_, DIM_);
    // 8. out = x1 + mid @ w2 + b2
    sgemm_kernel<0, true><<<dim3(DIM_/128, NTOK/128), 256>>>(
        mid, w2, b2, x1, out, NTOK, DIM_, FFN_);
}

// round 3
// speedup vs baseline: 2.5421x; 2.5421x over previous
#include <cuda_runtime.h>
#include <cuda_fp16.h>
#include <math.h>
#include <stdint.h>

#define B_    2
#define S_    2048
#define DIM_  1024
#define H_    16
#define HD_   64
#define FFN_  4096
#define NTOK  (B_*S_)

// ----------------------------------------------------------------------
// Scratch buffers (device globals; no allocation anywhere)
// ----------------------------------------------------------------------
__device__ __half g_h16[NTOK*DIM_];
__device__ float  g_qkv[NTOK*3*DIM_];
__device__ float  g_q[NTOK*DIM_];
__device__ float  g_k[NTOK*DIM_];
__device__ float  g_v[NTOK*DIM_];
__device__ __half g_ctx16[NTOK*DIM_];
__device__ float  g_x1[NTOK*DIM_];
__device__ __half g_mid16[NTOK*FFN_];
__device__ __half g_qkvw16[DIM_*3*DIM_];
__device__ __half g_outw16[DIM_*DIM_];
__device__ __half g_w116[DIM_*FFN_];
__device__ __half g_w216[FFN_*DIM_];

// ----------------------------------------------------------------------
// fp32 -> fp16 conversion
// ----------------------------------------------------------------------
__global__ void __launch_bounds__(256) f2h_kernel(
    const float4* __restrict__ s, __half2* __restrict__ d, int n4)
{
    int i = blockIdx.x * blockDim.x + threadIdx.x;
    if (i < n4) {
        float4 v = s[i];
        d[2*i]   = __floats2half2_rn(v.x, v.y);
        d[2*i+1] = __floats2half2_rn(v.z, v.w);
    }
}

// ----------------------------------------------------------------------
// LayerNorm: fp32 in, fp16 out. One block per row, 256 threads.
// ----------------------------------------------------------------------
__global__ void __launch_bounds__(256) ln_kernel(
    const float* __restrict__ x, const float* __restrict__ gw,
    const float* __restrict__ bw, __half* __restrict__ y)
{
    int row = blockIdx.x;
    int tid = threadIdx.x;
    float4 v = ((const float4*)(x + (size_t)row*DIM_))[tid];
    float s  = v.x + v.y + v.z + v.w;
    float ss = v.x*v.x + v.y*v.y + v.z*v.z + v.w*v.w;
    #pragma unroll
    for (int o = 16; o; o >>= 1) {
        s  += __shfl_xor_sync(0xffffffffu, s,  o);
        ss += __shfl_xor_sync(0xffffffffu, ss, o);
    }
    __shared__ float sm1[8];
    __shared__ float sm2[8];
    int w = tid >> 5;
    if ((tid & 31) == 0) { sm1[w] = s; sm2[w] = ss; }
    __syncthreads();
    s = 0.f; ss = 0.f;
    #pragma unroll
    for (int i = 0; i < 8; i++) { s += sm1[i]; ss += sm2[i]; }
    float mu  = s * (1.0f/1024.0f);
    float var = ss * (1.0f/1024.0f) - mu*mu;
    float r   = rsqrtf(var + 1e-5f);
    float4 g4 = ((const float4*)gw)[tid];
    float4 b4 = ((const float4*)bw)[tid];
    __half2 h0 = __floats2half2_rn((v.x - mu)*r*g4.x + b4.x, (v.y - mu)*r*g4.y + b4.y);
    __half2 h1 = __floats2half2_rn((v.z - mu)*r*g4.z + b4.z, (v.w - mu)*r*g4.w + b4.w);
    __half2* yp = (__half2*)(y + (size_t)row*DIM_);
    yp[tid*2]   = h0;
    yp[tid*2+1] = h1;
}

// ----------------------------------------------------------------------
// Tensor-core HGEMM: C[M,N] = A[M,K]*B[K,N] + bias, optional GELU / residual.
// 128x128x32 block tile, 256 threads (8 warps as 2x4), warp tile 64x32.
// mma.sync.m16n8k16 f32.f16.f16.f32, cp.async double buffer, swizzled smem.
// ----------------------------------------------------------------------
#define BM 128
#define BN 128
#define BK 32

__device__ __forceinline__ void ldsm4(uint32_t* r, uint32_t addr)
{
    asm volatile("ldmatrix.sync.aligned.m8n8.x4.shared.b16 {%0,%1,%2,%3}, [%4];"
        : "=r"(r[0]), "=r"(r[1]), "=r"(r[2]), "=r"(r[3]) : "r"(addr));
}

__device__ __forceinline__ void ldsm2t(uint32_t* r, uint32_t addr)
{
    asm volatile("ldmatrix.sync.aligned.m8n8.x2.trans.shared.b16 {%0,%1}, [%2];"
        : "=r"(r[0]), "=r"(r[1]) : "r"(addr));
}

__device__ __forceinline__ void mma16816(float* c, const uint32_t* a, const uint32_t* b)
{
    asm volatile("mma.sync.aligned.m16n8k16.row.col.f32.f16.f16.f32 "
        "{%0,%1,%2,%3}, {%4,%5,%6,%7}, {%8,%9}, {%0,%1,%2,%3};"
        : "+f"(c[0]), "+f"(c[1]), "+f"(c[2]), "+f"(c[3])
        : "r"(a[0]), "r"(a[1]), "r"(a[2]), "r"(a[3]), "r"(b[0]), "r"(b[1]));
}

__device__ __forceinline__ void cpa16(uint32_t dst, const void* src)
{
    asm volatile("cp.async.cg.shared.global [%0], [%1], 16;" :: "r"(dst), "l"(src));
}

__device__ __forceinline__ void cpa_commit()
{
    asm volatile("cp.async.commit_group;");
}

__device__ __forceinline__ void cpa_wait1()
{
    asm volatile("cp.async.wait_group 1;");
}

__device__ __forceinline__ void cpa_wait0()
{
    asm volatile("cp.async.wait_group 0;");
}

template<int ACT, int RES, int OUT16>
__global__ void __launch_bounds__(256, 2) hgemm_kernel(
    const __half* __restrict__ A, const __half* __restrict__ Bm,
    const float* __restrict__ bias, const float* __restrict__ res,
    void* __restrict__ Cout, int M, int N, int K)
{
    __shared__ __half As[2][BM*BK];
    __shared__ __half Bs[2][BK*BN];
    const uint32_t ABUF = BM*BK*2;
    const uint32_t BBUF = BK*BN*2;

    int tid  = threadIdx.x;
    int lane = tid & 31;
    int warp = tid >> 5;
    int wm = (warp >> 2) * 64;
    int wn = (warp & 3) * 32;
    int row0 = blockIdx.y * BM;
    int col0 = blockIdx.x * BN;

    int am = tid >> 1;
    int ac = (tid & 1) * 2;
    int bk = tid >> 3;
    int bg = (tid & 7) * 2;

    const __half* Ag = A  + (size_t)(row0 + am)*K + ac*8;
    const __half* Bg = Bm + (size_t)bk*N + col0 + bg*8;

    uint32_t sA = (uint32_t)__cvta_generic_to_shared(&As[0][0]);
    uint32_t sB = (uint32_t)__cvta_generic_to_shared(&Bs[0][0]);
    uint32_t aOff0 = (uint32_t)(am*32 + ((ac  ) ^ (am & 3))*8) * 2u;
    uint32_t aOff1 = (uint32_t)(am*32 + ((ac+1) ^ (am & 3))*8) * 2u;
    uint32_t bOff0 = (uint32_t)(bk*128 + ((bg  ) ^ (bk & 7))*8) * 2u;
    uint32_t bOff1 = (uint32_t)(bk*128 + ((bg+1) ^ (bk & 7))*8) * 2u;

    float acc[4][4][4];
    #pragma unroll
    for (int i = 0; i < 4; i++)
        #pragma unroll
        for (int j = 0; j < 4; j++)
            #pragma unroll
            for (int t = 0; t < 4; t++)
                acc[i][j][t] = 0.f;

    int nIt = K / BK;

    cpa16(sA + aOff0, Ag);
    cpa16(sA + aOff1, Ag + 8);
    cpa16(sB + bOff0, Bg);
    cpa16(sB + bOff1, Bg + 8);
    cpa_commit();

    int buf = 0;
    for (int it = 0; it < nIt; it++) {
        if (it + 1 < nIt) {
            uint32_t d = (uint32_t)(buf ^ 1);
            cpa16(sA + d*ABUF + aOff0, Ag + (it+1)*BK);
            cpa16(sA + d*ABUF + aOff1, Ag + (it+1)*BK + 8);
            cpa16(sB + d*BBUF + bOff0, Bg + (size_t)(it+1)*BK*N);
            cpa16(sB + d*BBUF + bOff1, Bg + (size_t)(it+1)*BK*N + 8);
            cpa_commit();
            cpa_wait1();
        } else {
            cpa_wait0();
        }
        __syncthreads();

        #pragma unroll
        for (int ks = 0; ks < 2; ks++) {
            uint32_t afr[4][4];
            uint32_t bfr[4][2];
            #pragma unroll
            for (int mt = 0; mt < 4; mt++) {
                int m  = wm + mt*16 + (lane & 15);
                int kg = ks*2 + (lane >> 4);
                uint32_t ad = sA + (uint32_t)buf*ABUF
                            + (uint32_t)(m*32 + ((kg ^ (m & 3))*8)) * 2u;
                ldsm4(afr[mt], ad);
            }
            #pragma unroll
            for (int nt = 0; nt < 4; nt++) {
                int r = ks*16 + (lane & 15);
                int g = ((wn + nt*8) >> 3) ^ (r & 7);
                uint32_t bd = sB + (uint32_t)buf*BBUF
                            + (uint32_t)(r*128 + g*8) * 2u;
                ldsm2t(bfr[nt], bd);
            }
            #pragma unroll
            for (int mt = 0; mt < 4; mt++)
                #pragma unroll
                for (int nt = 0; nt < 4; nt++)
                    mma16816(acc[mt][nt], afr[mt], bfr[nt]);
        }
        __syncthreads();
        buf ^= 1;
    }

    #pragma unroll
    for (int mt = 0; mt < 4; mt++) {
        #pragma unroll
        for (int hh = 0; hh < 2; hh++) {
            int r = row0 + wm + mt*16 + (lane >> 2) + hh*8;
            #pragma unroll
            for (int nt = 0; nt < 4; nt++) {
                int cc = col0 + wn + nt*8 + (lane & 3)*2;
                float v0 = acc[mt][nt][hh*2+0] + bias[cc];
                float v1 = acc[mt][nt][hh*2+1] + bias[cc+1];
                if (ACT == 1) {
                    v0 = 0.5f*v0*(1.0f + erff(v0*0.70710678f));
                    v1 = 0.5f*v1*(1.0f + erff(v1*0.70710678f));
                }
                if (RES == 1) {
                    float2 rr = *(const float2*)(res + (size_t)r*N + cc);
                    v0 += rr.x;
                    v1 += rr.y;
                }
                if (OUT16 == 1) {
                    __half* cp = (__half*)Cout + (size_t)r*N + cc;
                    *(__half2*)cp = __floats2half2_rn(v0, v1);
                } else {
                    float* cp = (float*)Cout + (size_t)r*N + cc;
                    *(float2*)cp = make_float2(v0, v1);
                }
            }
        }
    }
}

// ----------------------------------------------------------------------
// RoPE + QKV split: qkv [NTOK,3*DIM] -> Q/K/V [B,H,S,HD]
// ----------------------------------------------------------------------
__global__ void __launch_bounds__(256) rope_kernel(
    const float* __restrict__ qkv,
    float* __restrict__ Q, float* __restrict__ K, float* __restrict__ V)
{
    int idx = blockIdx.x * blockDim.x + threadIdx.x;
    int d = idx & 31;
    int h = (idx >> 5) & 15;
    int s = (idx >> 9) & 2047;
    int b = idx >> 20;
    int t = b*S_ + s;
    size_t base = (size_t)t*3072 + h*64 + d;
    float q1 = qkv[base];
    float q2 = qkv[base + 32];
    float k1 = qkv[base + 1024];
    float k2 = qkv[base + 1056];
    float v1 = qkv[base + 2048];
    float v2 = qkv[base + 2080];
    float inv = powf(10000.0f, -(float)d * (1.0f/32.0f));
    float ang = (float)s * inv;
    float sn, cs;
    sincosf(ang, &sn, &cs);
    size_t o = ((size_t)(b*H_ + h)*S_ + s)*64 + d;
    Q[o]      = q1*cs - q2*sn;
    Q[o + 32] = q2*cs + q1*sn;
    K[o]      = k1*cs - k2*sn;
    K[o + 32] = k2*cs + k1*sn;
    V[o]      = v1;
    V[o + 32] = v2;
}

// ----------------------------------------------------------------------
// Flash attention, fp32 math, fp16 ctx output.
// ----------------------------------------------------------------------
__global__ void __launch_bounds__(256) attn_kernel(
    const float* __restrict__ Q, const float* __restrict__ K,
    const float* __restrict__ V, const unsigned char* __restrict__ mask,
    __half* __restrict__ O)
{
    extern __shared__ float sm[];
    float* q_s = sm;
    float* k_s = sm + 4096;
    float* v_s = sm + 8192;
    float* p_s = sm + 12288;
    float* mk  = sm + 16384;

    int tid = threadIdx.x;
    int tx = tid & 15;
    int ty = tid >> 4;
    int bh = blockIdx.y;
    int b  = bh >> 4;
    int h  = bh & 15;
    int qt = blockIdx.x;
    const float* Qb = Q + ((size_t)bh*S_ + (size_t)qt*64)*64;
    const float* Kb = K + (size_t)bh*S_*64;
    const float* Vb = V + (size_t)bh*S_*64;

    {
        int i0 = tid >> 4;
        int d4 = (tid & 15) << 2;
        #pragma unroll
        for (int rep = 0; rep < 4; rep++) {
            int i = i0 + rep*16;
            *(float4*)&q_s[i*64 + d4] = *(const float4*)&Qb[(size_t)i*64 + d4];
        }
    }

    float m[4], l[4], acc[4][4];
    #pragma unroll
    for (int i = 0; i < 4; i++) {
        m[i] = -3.0e38f;
        l[i] = 0.f;
        #pragma unroll
        for (int j = 0; j < 4; j++) acc[i][j] = 0.f;
    }

    int xo = tx & 7;
    for (int kt = 0; kt < 32; kt++) {
        __syncthreads();
        {
            int j0 = tid >> 4;
            int g  = tid & 15;
            #pragma unroll
            for (int rep = 0; rep < 4; rep++) {
                int j = j0 + rep*16;
                float4 kv = *(const float4*)&Kb[((size_t)kt*64 + j)*64 + g*4];
                int gp = g ^ ((j >> 2) & 7);
                *(float4*)&k_s[j*64 + gp*4] = kv;
                *(float4*)&v_s[j*64 + g*4]  = *(const float4*)&Vb[((size_t)kt*64 + j)*64 + g*4];
            }
            if (tid < 64)
                mk[tid] = mask[(size_t)b*S_ + kt*64 + tid] ? -3.0e38f : 0.0f;
        }
        __syncthreads();

        float sc[4][4];
        #pragma unroll
        for (int i = 0; i < 4; i++)
            #pragma unroll
            for (int j = 0; j < 4; j++) sc[i][j] = 0.f;
        #pragma unroll
        for (int g = 0; g < 16; g++) {
            float4 qv[4], kv[4];
            #pragma unroll
            for (int i = 0; i < 4; i++)
                qv[i] = *(float4*)&q_s[(ty*4 + i)*64 + g*4];
            int gp = (g ^ xo) * 4;
            #pragma unroll
            for (int j = 0; j < 4; j++)
                kv[j] = *(float4*)&k_s[(tx*4 + j)*64 + gp];
            #pragma unroll
            for (int i = 0; i < 4; i++)
                #pragma unroll
                for (int j = 0; j < 4; j++)
                    sc[i][j] += qv[i].x*kv[j].x + qv[i].y*kv[j].y
                              + qv[i].z*kv[j].z + qv[i].w*kv[j].w;
        }

        #pragma unroll
        for (int i = 0; i < 4; i++) {
            float rmax = -3.0e38f;
            #pragma unroll
            for (int j = 0; j < 4; j++) {
                sc[i][j] = sc[i][j]*0.125f + mk[tx*4 + j];
                rmax = fmaxf(rmax, sc[i][j]);
            }
            #pragma unroll
            for (int o = 8; o >= 1; o >>= 1)
                rmax = fmaxf(rmax, __shfl_xor_sync(0xffffffffu, rmax, o, 16));
            float mn   = fmaxf(m[i], rmax);
            float corr = __expf(m[i] - mn);
            float p[4];
            float rsum = 0.f;
            #pragma unroll
            for (int j = 0; j < 4; j++) {
                p[j] = expf(sc[i][j] - mn);
                rsum += p[j];
            }
            #pragma unroll
            for (int o = 8; o >= 1; o >>= 1)
                rsum += __shfl_xor_sync(0xffffffffu, rsum, o, 16);
            m[i] = mn;
            l[i] = l[i]*corr + rsum;
            #pragma unroll
            for (int j = 0; j < 4; j++) acc[i][j] *= corr;
            *(float4*)&p_s[(ty*4 + i)*64 + tx*4] = make_float4(p[0], p[1], p[2], p[3]);
        }
        __syncthreads();

        #pragma unroll
        for (int j4 = 0; j4 < 16; j4++) {
            float4 pv[4], vv[4];
            #pragma unroll
            for (int i = 0; i < 4; i++)
                pv[i] = *(float4*)&p_s[(ty*4 + i)*64 + j4*4];
            #pragma unroll
            for (int j = 0; j < 4; j++)
                vv[j] = *(float4*)&v_s[(j4*4 + j)*64 + tx*4];
            #pragma unroll
            for (int i = 0; i < 4; i++) {
                acc[i][0] += pv[i].x*vv[0].x + pv[i].y*vv[1].x + pv[i].z*vv[2].x + pv[i].w*vv[3].x;
                acc[i][1] += pv[i].x*vv[0].y + pv[i].y*vv[1].y + pv[i].z*vv[2].y + pv[i].w*vv[3].y;
                acc[i][2] += pv[i].x*vv[0].z + pv[i].y*vv[1].z + pv[i].z*vv[2].z + pv[i].w*vv[3].z;
                acc[i][3] += pv[i].x*vv[0].w + pv[i].y*vv[1].w + pv[i].z*vv[2].w + pv[i].w*vv[3].w;
            }
        }
    }

    #pragma unroll
    for (int i = 0; i < 4; i++) {
        float inv = 1.0f / l[i];
        int row = qt*64 + ty*4 + i;
        size_t o = ((size_t)b*S_ + row)*DIM_ + h*64 + tx*4;
        *(__half2*)&O[o]     = __floats2half2_rn(acc[i][0]*inv, acc[i][1]*inv);
        *(__half2*)&O[o + 2] = __floats2half2_rn(acc[i][2]*inv, acc[i][3]*inv);
    }
}

// ----------------------------------------------------------------------
// Orchestration
// ----------------------------------------------------------------------
extern "C" void kernel_launch(void* const* d_in, const int* in_sizes, int n_in,
                              void* d_out, int out_size)
{
    (void)in_sizes; (void)n_in; (void)out_size;
    const float*         x     = (const float*)d_in[0];
    const unsigned char* mask  = (const unsigned char*)d_in[1];
    const float*         qkv_w = (const float*)d_in[2];
    const float*         qkv_b = (const float*)d_in[3];
    const float*         out_w = (const float*)d_in[4];
    const float*         out_b = (const float*)d_in[5];
    const float*         ln1_g = (const float*)d_in[6];
    const float*         ln1_b = (const float*)d_in[7];
    const float*         ln2_g = (const float*)d_in[8];
    const float*         ln2_b = (const float*)d_in[9];
    const float*         w1    = (const float*)d_in[10];
    const float*         b1    = (const float*)d_in[11];
    const float*         w2    = (const float*)d_in[12];
    const float*         b2    = (const float*)d_in[13];
    float* out = (float*)d_out;

    __half* h16;
    __half* ctx16;
    __half* mid16;
    __half* qkvw16;
    __half* outw16;
    __half* w116;
    __half* w216;
    float* qkv;
    float* q;
    float* k;
    float* v;
    float* x1;
    cudaGetSymbolAddress((void**)&h16,    g_h16);
    cudaGetSymbolAddress((void**)&qkv,    g_qkv);
    cudaGetSymbolAddress((void**)&q,      g_q);
    cudaGetSymbolAddress((void**)&k,      g_k);
    cudaGetSymbolAddress((void**)&v,      g_v);
    cudaGetSymbolAddress((void**)&ctx16,  g_ctx16);
    cudaGetSymbolAddress((void**)&x1,     g_x1);
    cudaGetSymbolAddress((void**)&mid16,  g_mid16);
    cudaGetSymbolAddress((void**)&qkvw16, g_qkvw16);
    cudaGetSymbolAddress((void**)&outw16, g_outw16);
    cudaGetSymbolAddress((void**)&w116,   g_w116);
    cudaGetSymbolAddress((void**)&w216,   g_w216);

    const int ATTN_SMEM = (4*64*64 + 64) * (int)sizeof(float);
    cudaFuncSetAttribute(attn_kernel, cudaFuncAttributeMaxDynamicSharedMemorySize,
                         ATTN_SMEM);

    f2h_kernel<<<DIM_*3*DIM_/4/256, 256>>>((const float4*)qkv_w, (__half2*)qkvw16, DIM_*3*DIM_/4);
    f2h_kernel<<<DIM_*DIM_/4/256,   256>>>((const float4*)out_w, (__half2*)outw16, DIM_*DIM_/4);
    f2h_kernel<<<DIM_*FFN_/4/256,   256>>>((const float4*)w1,    (__half2*)w116,   DIM_*FFN_/4);
    f2h_kernel<<<FFN_*DIM_/4/256,   256>>>((const float4*)w2,    (__half2*)w216,   FFN_*DIM_/4);

    ln_kernel<<<NTOK, 256>>>(x, ln1_g, ln1_b, h16);

    hgemm_kernel<0, 0, 0><<<dim3(3*DIM_/BN, NTOK/BM), 256>>>(
        h16, qkvw16, qkv_b, (const float*)0, (void*)qkv, NTOK, 3*DIM_, DIM_);

    rope_kernel<<<(NTOK*H_*32)/256, 256>>>(qkv, q, k, v);

    attn_kernel<<<dim3(S_/64, B_*H_), 256, ATTN_SMEM>>>(q, k, v, mask, ctx16);

    hgemm_kernel<0, 1, 0><<<dim3(DIM_/BN, NTOK/BM), 256>>>(
        ctx16, outw16, out_b, x, (void*)x1, NTOK, DIM_, DIM_);

    ln_kernel<<<NTOK, 256>>>(x1, ln2_g, ln2_b, h16);

    hgemm_kernel<1, 0, 1><<<dim3(FFN_/BN, NTOK/BM), 256>>>(
        h16, w116, b1, (const float*)0, (void*)mid16, NTOK, FFN_, DIM_);

    hgemm_kernel<0, 1, 0><<<dim3(DIM_/BN, NTOK/BM), 256>>>(
        mid16, w216, b2, x1, (void*)out, NTOK, DIM_, FFN_);
}

// round 4
// speedup vs baseline: 5.9934x; 2.3576x over previous
#include <cuda_runtime.h>
#include <cuda_fp16.h>
#include <math.h>
#include <stdint.h>

#define B_    2
#define S_    2048
#define DIM_  1024
#define H_    16
#define HD_   64
#define FFN_  4096
#define NTOK  (B_*S_)

// ----------------------------------------------------------------------
// Scratch buffers (device globals; no allocation anywhere)
// ----------------------------------------------------------------------
__device__ __half g_h16[NTOK*DIM_];
__device__ __half g_qkv16[NTOK*3*DIM_];
__device__ __half g_q16[NTOK*DIM_];
__device__ __half g_k16[NTOK*DIM_];
__device__ __half g_v16[NTOK*DIM_];
__device__ __half g_ctx16[NTOK*DIM_];
__device__ float  g_x1[NTOK*DIM_];
__device__ __half g_mid16[NTOK*FFN_];
__device__ __half g_qkvw16[DIM_*3*DIM_];
__device__ __half g_outw16[DIM_*DIM_];
__device__ __half g_w116[DIM_*FFN_];
__device__ __half g_w216[FFN_*DIM_];

// ----------------------------------------------------------------------
// PTX helpers
// ----------------------------------------------------------------------
__device__ __forceinline__ void ldsm4(uint32_t* r, uint32_t addr)
{
    asm volatile("ldmatrix.sync.aligned.m8n8.x4.shared.b16 {%0,%1,%2,%3}, [%4];"
        : "=r"(r[0]), "=r"(r[1]), "=r"(r[2]), "=r"(r[3]) : "r"(addr));
}

__device__ __forceinline__ void ldsm2t(uint32_t* r, uint32_t addr)
{
    asm volatile("ldmatrix.sync.aligned.m8n8.x2.trans.shared.b16 {%0,%1}, [%2];"
        : "=r"(r[0]), "=r"(r[1]) : "r"(addr));
}

__device__ __forceinline__ void mma16816(float* c, const uint32_t* a, const uint32_t* b)
{
    asm volatile("mma.sync.aligned.m16n8k16.row.col.f32.f16.f16.f32 "
        "{%0,%1,%2,%3}, {%4,%5,%6,%7}, {%8,%9}, {%0,%1,%2,%3};"
        : "+f"(c[0]), "+f"(c[1]), "+f"(c[2]), "+f"(c[3])
        : "r"(a[0]), "r"(a[1]), "r"(a[2]), "r"(a[3]), "r"(b[0]), "r"(b[1]));
}

__device__ __forceinline__ void cpa16(uint32_t dst, const void* src)
{
    asm volatile("cp.async.cg.shared.global [%0], [%1], 16;" :: "r"(dst), "l"(src));
}

__device__ __forceinline__ void cpa_commit()
{
    asm volatile("cp.async.commit_group;");
}

__device__ __forceinline__ void cpa_wait1()
{
    asm volatile("cp.async.wait_group 1;");
}

__device__ __forceinline__ void cpa_wait0()
{
    asm volatile("cp.async.wait_group 0;");
}

__device__ __forceinline__ uint32_t h2u(__half2 h)
{
    return *(uint32_t*)&h;
}

// ----------------------------------------------------------------------
// fp32 -> fp16 conversion
// ----------------------------------------------------------------------
__global__ void __launch_bounds__(256) f2h_kernel(
    const float4* __restrict__ s, __half2* __restrict__ d, int n4)
{
    int i = blockIdx.x * blockDim.x + threadIdx.x;
    if (i < n4) {
        float4 v = s[i];
        d[2*i]   = __floats2half2_rn(v.x, v.y);
        d[2*i+1] = __floats2half2_rn(v.z, v.w);
    }
}

// ----------------------------------------------------------------------
// LayerNorm: fp32 in, fp16 out.
// ----------------------------------------------------------------------
__global__ void __launch_bounds__(256) ln_kernel(
    const float* __restrict__ x, const float* __restrict__ gw,
    const float* __restrict__ bw, __half* __restrict__ y)
{
    int row = blockIdx.x;
    int tid = threadIdx.x;
    float4 v = ((const float4*)(x + (size_t)row*DIM_))[tid];
    float s  = v.x + v.y + v.z + v.w;
    float ss = v.x*v.x + v.y*v.y + v.z*v.z + v.w*v.w;
    #pragma unroll
    for (int o = 16; o; o >>= 1) {
        s  += __shfl_xor_sync(0xffffffffu, s,  o);
        ss += __shfl_xor_sync(0xffffffffu, ss, o);
    }
    __shared__ float sm1[8];
    __shared__ float sm2[8];
    int w = tid >> 5;
    if ((tid & 31) == 0) { sm1[w] = s; sm2[w] = ss; }
    __syncthreads();
    s = 0.f; ss = 0.f;
    #pragma unroll
    for (int i = 0; i < 8; i++) { s += sm1[i]; ss += sm2[i]; }
    float mu  = s * (1.0f/1024.0f);
    float var = ss * (1.0f/1024.0f) - mu*mu;
    float r   = rsqrtf(var + 1e-5f);
    float4 g4 = ((const float4*)gw)[tid];
    float4 b4 = ((const float4*)bw)[tid];
    __half2 h0 = __floats2half2_rn((v.x - mu)*r*g4.x + b4.x, (v.y - mu)*r*g4.y + b4.y);
    __half2 h1 = __floats2half2_rn((v.z - mu)*r*g4.z + b4.z, (v.w - mu)*r*g4.w + b4.w);
    __half2* yp = (__half2*)(y + (size_t)row*DIM_);
    yp[tid*2]   = h0;
    yp[tid*2+1] = h1;
}

// ----------------------------------------------------------------------
// Tensor-core HGEMM (as validated in round 3)
// ----------------------------------------------------------------------
#define BM 128
#define BN 128
#define BK 32

template<int ACT, int RES, int OUT16>
__global__ void __launch_bounds__(256, 2) hgemm_kernel(
    const __half* __restrict__ A, const __half* __restrict__ Bm,
    const float* __restrict__ bias, const float* __restrict__ res,
    void* __restrict__ Cout, int M, int N, int K)
{
    __shared__ __half As[2][BM*BK];
    __shared__ __half Bs[2][BK*BN];
    const uint32_t ABUF = BM*BK*2;
    const uint32_t BBUF = BK*BN*2;

    int tid  = threadIdx.x;
    int lane = tid & 31;
    int warp = tid >> 5;
    int wm = (warp >> 2) * 64;
    int wn = (warp & 3) * 32;
    int row0 = blockIdx.y * BM;
    int col0 = blockIdx.x * BN;

    int am = tid >> 1;
    int ac = (tid & 1) * 2;
    int bk = tid >> 3;
    int bg = (tid & 7) * 2;

    const __half* Ag = A  + (size_t)(row0 + am)*K + ac*8;
    const __half* Bg = Bm + (size_t)bk*N + col0 + bg*8;

    uint32_t sA = (uint32_t)__cvta_generic_to_shared(&As[0][0]);
    uint32_t sB = (uint32_t)__cvta_generic_to_shared(&Bs[0][0]);
    uint32_t aOff0 = (uint32_t)(am*32 + ((ac  ) ^ (am & 3))*8) * 2u;
    uint32_t aOff1 = (uint32_t)(am*32 + ((ac+1) ^ (am & 3))*8) * 2u;
    uint32_t bOff0 = (uint32_t)(bk*128 + ((bg  ) ^ (bk & 7))*8) * 2u;
    uint32_t bOff1 = (uint32_t)(bk*128 + ((bg+1) ^ (bk & 7))*8) * 2u;

    float acc[4][4][4];
    #pragma unroll
    for (int i = 0; i < 4; i++)
        #pragma unroll
        for (int j = 0; j < 4; j++)
            #pragma unroll
            for (int t = 0; t < 4; t++)
                acc[i][j][t] = 0.f;

    int nIt = K / BK;

    cpa16(sA + aOff0, Ag);
    cpa16(sA + aOff1, Ag + 8);
    cpa16(sB + bOff0, Bg);
    cpa16(sB + bOff1, Bg + 8);
    cpa_commit();

    int buf = 0;
    for (int it = 0; it < nIt; it++) {
        if (it + 1 < nIt) {
            uint32_t d = (uint32_t)(buf ^ 1);
            cpa16(sA + d*ABUF + aOff0, Ag + (it+1)*BK);
            cpa16(sA + d*ABUF + aOff1, Ag + (it+1)*BK + 8);
            cpa16(sB + d*BBUF + bOff0, Bg + (size_t)(it+1)*BK*N);
            cpa16(sB + d*BBUF + bOff1, Bg + (size_t)(it+1)*BK*N + 8);
            cpa_commit();
            cpa_wait1();
        } else {
            cpa_wait0();
        }
        __syncthreads();

        #pragma unroll
        for (int ks = 0; ks < 2; ks++) {
            uint32_t afr[4][4];
            uint32_t bfr[4][2];
            #pragma unroll
            for (int mt = 0; mt < 4; mt++) {
                int m  = wm + mt*16 + (lane & 15);
                int kg = ks*2 + (lane >> 4);
                uint32_t ad = sA + (uint32_t)buf*ABUF
                            + (uint32_t)(m*32 + ((kg ^ (m & 3))*8)) * 2u;
                ldsm4(afr[mt], ad);
            }
            #pragma unroll
            for (int nt = 0; nt < 4; nt++) {
                int r = ks*16 + (lane & 15);
                int g = ((wn + nt*8) >> 3) ^ (r & 7);
                uint32_t bd = sB + (uint32_t)buf*BBUF
                            + (uint32_t)(r*128 + g*8) * 2u;
                ldsm2t(bfr[nt], bd);
            }
            #pragma unroll
            for (int mt = 0; mt < 4; mt++)
                #pragma unroll
                for (int nt = 0; nt < 4; nt++)
                    mma16816(acc[mt][nt], afr[mt], bfr[nt]);
        }
        __syncthreads();
        buf ^= 1;
    }

    #pragma unroll
    for (int mt = 0; mt < 4; mt++) {
        #pragma unroll
        for (int hh = 0; hh < 2; hh++) {
            int r = row0 + wm + mt*16 + (lane >> 2) + hh*8;
            #pragma unroll
            for (int nt = 0; nt < 4; nt++) {
                int cc = col0 + wn + nt*8 + (lane & 3)*2;
                float v0 = acc[mt][nt][hh*2+0] + bias[cc];
                float v1 = acc[mt][nt][hh*2+1] + bias[cc+1];
                if (ACT == 1) {
                    v0 = 0.5f*v0*(1.0f + erff(v0*0.70710678f));
                    v1 = 0.5f*v1*(1.0f + erff(v1*0.70710678f));
                }
                if (RES == 1) {
                    float2 rr = *(const float2*)(res + (size_t)r*N + cc);
                    v0 += rr.x;
                    v1 += rr.y;
                }
                if (OUT16 == 1) {
                    __half* cp = (__half*)Cout + (size_t)r*N + cc;
                    *(__half2*)cp = __floats2half2_rn(v0, v1);
                } else {
                    float* cp = (float*)Cout + (size_t)r*N + cc;
                    *(float2*)cp = make_float2(v0, v1);
                }
            }
        }
    }
}

// ----------------------------------------------------------------------
// RoPE + split: fp16 qkv [NTOK,3*DIM] -> fp16 Q (prescaled 0.125), K, V
// ----------------------------------------------------------------------
__global__ void __launch_bounds__(256) rope_kernel(
    const __half* __restrict__ qkv,
    __half* __restrict__ Q, __half* __restrict__ K, __half* __restrict__ V)
{
    int idx = blockIdx.x * blockDim.x + threadIdx.x;
    int d = idx & 31;
    int h = (idx >> 5) & 15;
    int s = (idx >> 9) & 2047;
    int b = idx >> 20;
    int t = b*S_ + s;
    size_t base = (size_t)t*3072 + h*64 + d;
    float q1 = __half2float(qkv[base]);
    float q2 = __half2float(qkv[base + 32]);
    float k1 = __half2float(qkv[base + 1024]);
    float k2 = __half2float(qkv[base + 1056]);
    __half v1 = qkv[base + 2048];
    __half v2 = qkv[base + 2080];
    float inv = powf(10000.0f, -(float)d * (1.0f/32.0f));
    float ang = (float)s * inv;
    float sn, cs;
    sincosf(ang, &sn, &cs);
    size_t o = ((size_t)(b*H_ + h)*S_ + s)*64 + d;
    Q[o]      = __float2half((q1*cs - q2*sn) * 0.125f);
    Q[o + 32] = __float2half((q2*cs + q1*sn) * 0.125f);
    K[o]      = __float2half(k1*cs - k2*sn);
    K[o + 32] = __float2half(k2*cs + k1*sn);
    V[o]      = v1;
    V[o + 32] = v2;
}

// ----------------------------------------------------------------------
// Tensor-core flash attention.
// Block: 128 q rows x one (b,h). 256 threads = 8 warps, 16 rows each.
// Per 64-key tile: S = Q@K^T (HMMA), fp32 online softmax, P@V (HMMA).
// Q frags resident in registers; K/V double-buffered via cp.async.
// ----------------------------------------------------------------------
__global__ void __launch_bounds__(256) fattn_kernel(
    const __half* __restrict__ Q, const __half* __restrict__ K,
    const __half* __restrict__ V, const unsigned char* __restrict__ mask,
    __half* __restrict__ O)
{
    __shared__ __half sk[2][64*64];
    __shared__ __half sv[2][64*64];
    __shared__ float  smk[2][64];

    int tid  = threadIdx.x;
    int lane = tid & 31;
    int warp = tid >> 5;
    int bh = blockIdx.y;
    int b  = bh >> 4;
    int h  = bh & 15;
    int qt = blockIdx.x;

    const __half* Qb = Q + ((size_t)bh*S_ + (size_t)qt*128)*64;
    const __half* Kb = K + (size_t)bh*S_*64;
    const __half* Vb = V + (size_t)bh*S_*64;

    uint32_t skA = (uint32_t)__cvta_generic_to_shared(&sk[0][0]);
    uint32_t svA = (uint32_t)__cvta_generic_to_shared(&sv[0][0]);

    // Stage Q tile (128x64) into sk area, swizzled
    #pragma unroll
    for (int i = 0; i < 4; i++) {
        int c = tid + i*256;
        int r = c >> 3;
        int g = c & 7;
        uint32_t off = (uint32_t)(r*64 + ((g ^ (r & 7))*8)) * 2u;
        cpa16(skA + off, Qb + (size_t)r*64 + g*8);
    }
    cpa_commit();
    cpa_wait0();
    __syncthreads();

    // Build Q fragments: 4 k-steps of 16, held in registers
    uint32_t qf[4][4];
    {
        int row = warp*16 + (lane & 15);
        #pragma unroll
        for (int ks = 0; ks < 4; ks++) {
            int kg = ks*2 + (lane >> 4);
            uint32_t ad = skA + (uint32_t)(row*64 + ((kg ^ (row & 7))*8)) * 2u;
            ldsm4(qf[ks], ad);
        }
    }
    __syncthreads();   // Q staging done; sk reused for K tiles

    float m1 = -3.0e38f, m2 = -3.0e38f, l1 = 0.f, l2 = 0.f;
    float acc[8][4];
    #pragma unroll
    for (int nt = 0; nt < 8; nt++)
        #pragma unroll
        for (int t = 0; t < 4; t++)
            acc[nt][t] = 0.f;

    // prefetch KV tile 0 into buffer 0
    {
        int r = tid >> 2;
        #pragma unroll
        for (int j = 0; j < 2; j++) {
            int g = (tid & 3)*2 + j;
            uint32_t off = (uint32_t)(r*64 + ((g ^ (r & 7))*8)) * 2u;
            cpa16(skA + off, Kb + (size_t)r*64 + g*8);
            cpa16(svA + off, Vb + (size_t)r*64 + g*8);
        }
        if (tid < 64)
            smk[0][tid] = mask[(size_t)b*S_ + tid] ? -3.0e38f : 0.0f;
    }
    cpa_commit();

    const int NKT = S_/64;   // 32
    for (int kt = 0; kt < NKT; kt++) {
        int buf = kt & 1;
        if (kt + 1 < NKT) {
            int nb = buf ^ 1;
            const __half* Kt = Kb + (size_t)(kt+1)*64*64;
            const __half* Vt = Vb + (size_t)(kt+1)*64*64;
            int r = tid >> 2;
            #pragma unroll
            for (int j = 0; j < 2; j++) {
                int g = (tid & 3)*2 + j;
                uint32_t off = (uint32_t)(nb*8192 + (r*64 + ((g ^ (r & 7))*8))*2);
                cpa16(skA + off, Kt + (size_t)r*64 + g*8);
                cpa16(svA + off, Vt + (size_t)r*64 + g*8);
            }
            if (tid < 64)
                smk[nb][tid] = mask[(size_t)b*S_ + (kt+1)*64 + tid] ? -3.0e38f : 0.0f;
            cpa_commit();
            cpa_wait1();
        } else {
            cpa_wait0();
        }
        __syncthreads();

        // ---- S = Q @ K^T : 8 n-tiles of 8 key-cols ----
        float sc[8][4];
        #pragma unroll
        for (int nt = 0; nt < 8; nt++) {
            sc[nt][0] = 0.f; sc[nt][1] = 0.f; sc[nt][2] = 0.f; sc[nt][3] = 0.f;
            int mrow = nt*8 + (lane & 7);
            uint32_t kb0[4], kb1[4];
            {
                int kg = (lane >> 3);
                ldsm4(kb0, skA + (uint32_t)(buf*8192 + (mrow*64 + ((kg ^ (mrow & 7))*8))*2));
            }
            {
                int kg = 4 + (lane >> 3);
                ldsm4(kb1, skA + (uint32_t)(buf*8192 + (mrow*64 + ((kg ^ (mrow & 7))*8))*2));
            }
            mma16816(sc[nt], qf[0], kb0 + 0);
            mma16816(sc[nt], qf[1], kb0 + 2);
            mma16816(sc[nt], qf[2], kb1 + 0);
            mma16816(sc[nt], qf[3], kb1 + 2);
        }

        // ---- mask + online softmax (rows r1 = lane>>2, r2 = r1+8) ----
        float rmax1 = -3.0e38f, rmax2 = -3.0e38f;
        #pragma unroll
        for (int nt = 0; nt < 8; nt++) {
            int c0 = nt*8 + (lane & 3)*2;
            float k0 = smk[buf][c0];
            float k1 = smk[buf][c0 + 1];
            sc[nt][0] += k0; sc[nt][1] += k1;
            sc[nt][2] += k0; sc[nt][3] += k1;
            rmax1 = fmaxf(rmax1, fmaxf(sc[nt][0], sc[nt][1]));
            rmax2 = fmaxf(rmax2, fmaxf(sc[nt][2], sc[nt][3]));
        }
        rmax1 = fmaxf(rmax1, __shfl_xor_sync(0xffffffffu, rmax1, 1));
        rmax1 = fmaxf(rmax1, __shfl_xor_sync(0xffffffffu, rmax1, 2));
        rmax2 = fmaxf(rmax2, __shfl_xor_sync(0xffffffffu, rmax2, 1));
        rmax2 = fmaxf(rmax2, __shfl_xor_sync(0xffffffffu, rmax2, 2));

        float mn1 = fmaxf(m1, rmax1);
        float mn2 = fmaxf(m2, rmax2);
        float corr1 = __expf(m1 - mn1);
        float corr2 = __expf(m2 - mn2);
        float rs1 = 0.f, rs2 = 0.f;

        uint32_t pf[4][4];
        #pragma unroll
        for (int ktp = 0; ktp < 4; ktp++) {
            #pragma unroll
            for (int sub = 0; sub < 2; sub++) {
                int nt = ktp*2 + sub;
                float p0 = __expf(sc[nt][0] - mn1);
                float p1 = __expf(sc[nt][1] - mn1);
                float p2 = __expf(sc[nt][2] - mn2);
                float p3 = __expf(sc[nt][3] - mn2);
                rs1 += p0 + p1;
                rs2 += p2 + p3;
                pf[ktp][sub*2 + 0] = h2u(__floats2half2_rn(p0, p1));
                pf[ktp][sub*2 + 1] = h2u(__floats2half2_rn(p2, p3));
            }
        }
        rs1 += __shfl_xor_sync(0xffffffffu, rs1, 1);
        rs1 += __shfl_xor_sync(0xffffffffu, rs1, 2);
        rs2 += __shfl_xor_sync(0xffffffffu, rs2, 1);
        rs2 += __shfl_xor_sync(0xffffffffu, rs2, 2);

        m1 = mn1; m2 = mn2;
        l1 = l1*corr1 + rs1;
        l2 = l2*corr2 + rs2;
        #pragma unroll
        for (int nt = 0; nt < 8; nt++) {
            acc[nt][0] *= corr1; acc[nt][1] *= corr1;
            acc[nt][2] *= corr2; acc[nt][3] *= corr2;
        }

        // ---- acc += P @ V ----
        #pragma unroll
        for (int nt = 0; nt < 8; nt++) {
            #pragma unroll
            for (int ktp = 0; ktp < 4; ktp++) {
                uint32_t vb[2];
                int r = ktp*16 + (lane & 15);
                int g = nt ^ (r & 7);
                ldsm2t(vb, svA + (uint32_t)(buf*8192 + (r*64 + g*8)*2));
                mma16816(acc[nt], pf[ktp], vb);
            }
        }
        __syncthreads();
    }

    // ---- normalize + write ctx [b][s][h*64 + c] fp16 ----
    float il1 = 1.0f / l1;
    float il2 = 1.0f / l2;
    int r1 = qt*128 + warp*16 + (lane >> 2);
    int r2 = r1 + 8;
    size_t row1 = ((size_t)b*S_ + r1)*DIM_ + h*64;
    size_t row2 = ((size_t)b*S_ + r2)*DIM_ + h*64;
    #pragma unroll
    for (int nt = 0; nt < 8; nt++) {
        int c = nt*8 + (lane & 3)*2;
        *(__half2*)(O + row1 + c) = __floats2half2_rn(acc[nt][0]*il1, acc[nt][1]*il1);
        *(__half2*)(O + row2 + c) = __floats2half2_rn(acc[nt][2]*il2, acc[nt][3]*il2);
    }
}

// ----------------------------------------------------------------------
// Orchestration
// ----------------------------------------------------------------------
extern "C" void kernel_launch(void* const* d_in, const int* in_sizes, int n_in,
                              void* d_out, int out_size)
{
    (void)in_sizes; (void)n_in; (void)out_size;
    const float*         x     = (const float*)d_in[0];
    const unsigned char* mask  = (const unsigned char*)d_in[1];
    const float*         qkv_w = (const float*)d_in[2];
    const float*         qkv_b = (const float*)d_in[3];
    const float*         out_w = (const float*)d_in[4];
    const float*         out_b = (const float*)d_in[5];
    const float*         ln1_g = (const float*)d_in[6];
    const float*         ln1_b = (const float*)d_in[7];
    const float*         ln2_g = (const float*)d_in[8];
    const float*         ln2_b = (const float*)d_in[9];
    const float*         w1    = (const float*)d_in[10];
    const float*         b1    = (const float*)d_in[11];
    const float*         w2    = (const float*)d_in[12];
    const float*         b2    = (const float*)d_in[13];
    float* out = (float*)d_out;

    __half* h16;
    __half* qkv16;
    __half* q16;
    __half* k16;
    __half* v16;
    __half* ctx16;
    __half* mid16;
    __half* qkvw16;
    __half* outw16;
    __half* w116;
    __half* w216;
    float* x1;
    cudaGetSymbolAddress((void**)&h16,    g_h16);
    cudaGetSymbolAddress((void**)&qkv16,  g_qkv16);
    cudaGetSymbolAddress((void**)&q16,    g_q16);
    cudaGetSymbolAddress((void**)&k16,    g_k16);
    cudaGetSymbolAddress((void**)&v16,    g_v16);
    cudaGetSymbolAddress((void**)&ctx16,  g_ctx16);
    cudaGetSymbolAddress((void**)&x1,     g_x1);
    cudaGetSymbolAddress((void**)&mid16,  g_mid16);
    cudaGetSymbolAddress((void**)&qkvw16, g_qkvw16);
    cudaGetSymbolAddress((void**)&outw16, g_outw16);
    cudaGetSymbolAddress((void**)&w116,   g_w116);
    cudaGetSymbolAddress((void**)&w216,   g_w216);

    f2h_kernel<<<DIM_*3*DIM_/4/256, 256>>>((const float4*)qkv_w, (__half2*)qkvw16, DIM_*3*DIM_/4);
    f2h_kernel<<<DIM_*DIM_/4/256,   256>>>((const float4*)out_w, (__half2*)outw16, DIM_*DIM_/4);
    f2h_kernel<<<DIM_*FFN_/4/256,   256>>>((const float4*)w1,    (__half2*)w116,   DIM_*FFN_/4);
    f2h_kernel<<<FFN_*DIM_/4/256,   256>>>((const float4*)w2,    (__half2*)w216,   FFN_*DIM_/4);

    ln_kernel<<<NTOK, 256>>>(x, ln1_g, ln1_b, h16);

    hgemm_kernel<0, 0, 1><<<dim3(3*DIM_/BN, NTOK/BM), 256>>>(
        h16, qkvw16, qkv_b, (const float*)0, (void*)qkv16, NTOK, 3*DIM_, DIM_);

    rope_kernel<<<(NTOK*H_*32)/256, 256>>>(qkv16, q16, k16, v16);

    fattn_kernel<<<dim3(S_/128, B_*H_), 256>>>(q16, k16, v16, mask, ctx16);

    hgemm_kernel<0, 1, 0><<<dim3(DIM_/BN, NTOK/BM), 256>>>(
        ctx16, outw16, out_b, x, (void*)x1, NTOK, DIM_, DIM_);

    ln_kernel<<<NTOK, 256>>>(x1, ln2_g, ln2_b, h16);

    hgemm_kernel<1, 0, 1><<<dim3(FFN_/BN, NTOK/BM), 256>>>(
        h16, w116, b1, (const float*)0, (void*)mid16, NTOK, FFN_, DIM_);

    hgemm_kernel<0, 1, 0><<<dim3(DIM_/BN, NTOK/BM), 256>>>(
        mid16, w216, b2, x1, (void*)out, NTOK, DIM_, FFN_);
}

// round 5
// speedup vs baseline: 6.1552x; 1.0270x over previous
#include <cuda_runtime.h>
#include <cuda_fp16.h>
#include <math.h>
#include <stdint.h>

#define B_    2
#define S_    2048
#define DIM_  1024
#define H_    16
#define HD_   64
#define FFN_  4096
#define NTOK  (B_*S_)

// ----------------------------------------------------------------------
// Scratch buffers (device globals; no allocation anywhere)
// ----------------------------------------------------------------------
__device__ __half g_h16[NTOK*DIM_];
__device__ __half g_qkv16[NTOK*3*DIM_];
__device__ __half g_q16[NTOK*DIM_];
__device__ __half g_k16[NTOK*DIM_];
__device__ __half g_v16[NTOK*DIM_];
__device__ __half g_ctx16[NTOK*DIM_];
__device__ float  g_x1[NTOK*DIM_];
__device__ __half g_mid16[NTOK*FFN_];
__device__ __half g_qkvw16[DIM_*3*DIM_];
__device__ __half g_outw16[DIM_*DIM_];
__device__ __half g_w116[DIM_*FFN_];
__device__ __half g_w216[FFN_*DIM_];

// ----------------------------------------------------------------------
// PTX helpers
// ----------------------------------------------------------------------
__device__ __forceinline__ void ldsm4(uint32_t* r, uint32_t addr)
{
    asm volatile("ldmatrix.sync.aligned.m8n8.x4.shared.b16 {%0,%1,%2,%3}, [%4];"
        : "=r"(r[0]), "=r"(r[1]), "=r"(r[2]), "=r"(r[3]) : "r"(addr));
}

__device__ __forceinline__ void ldsm4t(uint32_t* r, uint32_t addr)
{
    asm volatile("ldmatrix.sync.aligned.m8n8.x4.trans.shared.b16 {%0,%1,%2,%3}, [%4];"
        : "=r"(r[0]), "=r"(r[1]), "=r"(r[2]), "=r"(r[3]) : "r"(addr));
}

__device__ __forceinline__ void ldsm2t(uint32_t* r, uint32_t addr)
{
    asm volatile("ldmatrix.sync.aligned.m8n8.x2.trans.shared.b16 {%0,%1}, [%2];"
        : "=r"(r[0]), "=r"(r[1]) : "r"(addr));
}

__device__ __forceinline__ void mma16816(float* c, const uint32_t* a, const uint32_t* b)
{
    asm volatile("mma.sync.aligned.m16n8k16.row.col.f32.f16.f16.f32 "
        "{%0,%1,%2,%3}, {%4,%5,%6,%7}, {%8,%9}, {%0,%1,%2,%3};"
        : "+f"(c[0]), "+f"(c[1]), "+f"(c[2]), "+f"(c[3])
        : "r"(a[0]), "r"(a[1]), "r"(a[2]), "r"(a[3]), "r"(b[0]), "r"(b[1]));
}

__device__ __forceinline__ void cpa16(uint32_t dst, const void* src)
{
    asm volatile("cp.async.cg.shared.global [%0], [%1], 16;" :: "r"(dst), "l"(src));
}

__device__ __forceinline__ void cpa_commit()
{
    asm volatile("cp.async.commit_group;");
}

__device__ __forceinline__ void cpa_wait1()
{
    asm volatile("cp.async.wait_group 1;");
}

__device__ __forceinline__ void cpa_wait0()
{
    asm volatile("cp.async.wait_group 0;");
}

__device__ __forceinline__ uint32_t h2u(__half2 h)
{
    return *(uint32_t*)&h;
}

// ----------------------------------------------------------------------
// fp32 -> fp16 conversion, 4 float4 per thread (MLP=4)
// ----------------------------------------------------------------------
__global__ void __launch_bounds__(256) f2h_kernel(
    const float4* __restrict__ s, __half2* __restrict__ d, int n4)
{
    int i0 = blockIdx.x * 1024 + threadIdx.x;
    #pragma unroll
    for (int u = 0; u < 4; u++) {
        int i = i0 + u*256;
        float4 v = s[i];
        d[2*i]   = __floats2half2_rn(v.x, v.y);
        d[2*i+1] = __floats2half2_rn(v.z, v.w);
    }
}

// ----------------------------------------------------------------------
// LayerNorm: fp32 in, fp16 out.
// ----------------------------------------------------------------------
__global__ void __launch_bounds__(256) ln_kernel(
    const float* __restrict__ x, const float* __restrict__ gw,
    const float* __restrict__ bw, __half* __restrict__ y)
{
    int row = blockIdx.x;
    int tid = threadIdx.x;
    float4 v = ((const float4*)(x + (size_t)row*DIM_))[tid];
    float s  = v.x + v.y + v.z + v.w;
    float ss = v.x*v.x + v.y*v.y + v.z*v.z + v.w*v.w;
    #pragma unroll
    for (int o = 16; o; o >>= 1) {
        s  += __shfl_xor_sync(0xffffffffu, s,  o);
        ss += __shfl_xor_sync(0xffffffffu, ss, o);
    }
    __shared__ float sm1[8];
    __shared__ float sm2[8];
    int w = tid >> 5;
    if ((tid & 31) == 0) { sm1[w] = s; sm2[w] = ss; }
    __syncthreads();
    s = 0.f; ss = 0.f;
    #pragma unroll
    for (int i = 0; i < 8; i++) { s += sm1[i]; ss += sm2[i]; }
    float mu  = s * (1.0f/1024.0f);
    float var = ss * (1.0f/1024.0f) - mu*mu;
    float r   = rsqrtf(var + 1e-5f);
    float4 g4 = ((const float4*)gw)[tid];
    float4 b4 = ((const float4*)bw)[tid];
    __half2 h0 = __floats2half2_rn((v.x - mu)*r*g4.x + b4.x, (v.y - mu)*r*g4.y + b4.y);
    __half2 h1 = __floats2half2_rn((v.z - mu)*r*g4.z + b4.z, (v.w - mu)*r*g4.w + b4.w);
    __half2* yp = (__half2*)(y + (size_t)row*DIM_);
    yp[tid*2]   = h0;
    yp[tid*2+1] = h1;
}

// ----------------------------------------------------------------------
// Tensor-core HGEMM, 3-stage cp.async pipeline, one sync per iteration.
// 128x128x32 block tile, 256 threads (8 warps 2x4), warp tile 64x32.
// ----------------------------------------------------------------------
#define BM 128
#define BN 128
#define BK 32

template<int ACT, int RES, int OUT16>
__global__ void __launch_bounds__(256, 2) hgemm_kernel(
    const __half* __restrict__ A, const __half* __restrict__ Bm,
    const float* __restrict__ bias, const float* __restrict__ res,
    void* __restrict__ Cout, int M, int N, int K)
{
    __shared__ __half As[3][BM*BK];
    __shared__ __half Bs[3][BK*BN];
    const uint32_t ABUF = BM*BK*2;
    const uint32_t BBUF = BK*BN*2;

    int tid  = threadIdx.x;
    int lane = tid & 31;
    int warp = tid >> 5;
    int wm = (warp >> 2) * 64;
    int wn = (warp & 3) * 32;
    int row0 = blockIdx.y * BM;
    int col0 = blockIdx.x * BN;

    int am = tid >> 1;
    int ac = (tid & 1) * 2;
    int bk = tid >> 3;
    int bg = (tid & 7) * 2;

    const __half* Ag = A  + (size_t)(row0 + am)*K + ac*8;
    const __half* Bg = Bm + (size_t)bk*N + col0 + bg*8;

    uint32_t sA = (uint32_t)__cvta_generic_to_shared(&As[0][0]);
    uint32_t sB = (uint32_t)__cvta_generic_to_shared(&Bs[0][0]);
    uint32_t aOff0 = (uint32_t)(am*32 + ((ac  ) ^ (am & 3))*8) * 2u;
    uint32_t aOff1 = (uint32_t)(am*32 + ((ac+1) ^ (am & 3))*8) * 2u;
    uint32_t bOff0 = (uint32_t)(bk*128 + ((bg  ) ^ (bk & 7))*8) * 2u;
    uint32_t bOff1 = (uint32_t)(bk*128 + ((bg+1) ^ (bk & 7))*8) * 2u;

    float acc[4][4][4];
    #pragma unroll
    for (int i = 0; i < 4; i++)
        #pragma unroll
        for (int j = 0; j < 4; j++)
            #pragma unroll
            for (int t = 0; t < 4; t++)
                acc[i][j][t] = 0.f;

    int nIt = K / BK;

    // prologue: stages 0 and 1
    cpa16(sA + aOff0, Ag);
    cpa16(sA + aOff1, Ag + 8);
    cpa16(sB + bOff0, Bg);
    cpa16(sB + bOff1, Bg + 8);
    cpa_commit();
    cpa16(sA + ABUF + aOff0, Ag + BK);
    cpa16(sA + ABUF + aOff1, Ag + BK + 8);
    cpa16(sB + BBUF + bOff0, Bg + (size_t)BK*N);
    cpa16(sB + BBUF + bOff1, Bg + (size_t)BK*N + 8);
    cpa_commit();

    for (int it = 0; it < nIt; it++) {
        if (it + 1 < nIt) cpa_wait1(); else cpa_wait0();
        __syncthreads();

        if (it + 2 < nIt) {
            uint32_t st = (uint32_t)((it + 2) % 3);
            cpa16(sA + st*ABUF + aOff0, Ag + (it+2)*BK);
            cpa16(sA + st*ABUF + aOff1, Ag + (it+2)*BK + 8);
            cpa16(sB + st*BBUF + bOff0, Bg + (size_t)(it+2)*BK*N);
            cpa16(sB + st*BBUF + bOff1, Bg + (size_t)(it+2)*BK*N + 8);
            cpa_commit();
        }

        uint32_t buf = (uint32_t)(it % 3);
        #pragma unroll
        for (int ks = 0; ks < 2; ks++) {
            uint32_t afr[4][4];
            uint32_t bfr[2][4];
            #pragma unroll
            for (int mt = 0; mt < 4; mt++) {
                int m  = wm + mt*16 + (lane & 15);
                int kg = ks*2 + (lane >> 4);
                uint32_t ad = sA + buf*ABUF
                            + (uint32_t)(m*32 + ((kg ^ (m & 3))*8)) * 2u;
                ldsm4(afr[mt], ad);
            }
            #pragma unroll
            for (int p = 0; p < 2; p++) {
                int r = ks*16 + (lane & 15);
                int n = wn + p*16 + ((lane >> 4)*8);
                int g = (n >> 3) ^ (r & 7);
                uint32_t bd = sB + buf*BBUF
                            + (uint32_t)(r*128 + g*8) * 2u;
                ldsm4t(bfr[p], bd);
            }
            #pragma unroll
            for (int mt = 0; mt < 4; mt++) {
                #pragma unroll
                for (int p = 0; p < 2; p++) {
                    mma16816(acc[mt][2*p],   afr[mt], bfr[p] + 0);
                    mma16816(acc[mt][2*p+1], afr[mt], bfr[p] + 2);
                }
            }
        }
    }

    __syncthreads();

    #pragma unroll
    for (int mt = 0; mt < 4; mt++) {
        #pragma unroll
        for (int hh = 0; hh < 2; hh++) {
            int r = row0 + wm + mt*16 + (lane >> 2) + hh*8;
            #pragma unroll
            for (int nt = 0; nt < 4; nt++) {
                int cc = col0 + wn + nt*8 + (lane & 3)*2;
                float v0 = acc[mt][nt][hh*2+0] + bias[cc];
                float v1 = acc[mt][nt][hh*2+1] + bias[cc+1];
                if (ACT == 1) {
                    v0 = 0.5f*v0*(1.0f + erff(v0*0.70710678f));
                    v1 = 0.5f*v1*(1.0f + erff(v1*0.70710678f));
                }
                if (RES == 1) {
                    float2 rr = *(const float2*)(res + (size_t)r*N + cc);
                    v0 += rr.x;
                    v1 += rr.y;
                }
                if (OUT16 == 1) {
                    __half* cp = (__half*)Cout + (size_t)r*N + cc;
                    *(__half2*)cp = __floats2half2_rn(v0, v1);
                } else {
                    float* cp = (float*)Cout + (size_t)r*N + cc;
                    *(float2*)cp = make_float2(v0, v1);
                }
            }
        }
    }
}

// ----------------------------------------------------------------------
// RoPE + split: fp16 qkv [NTOK,3*DIM] -> fp16 Q (prescaled 0.125), K, V
// ----------------------------------------------------------------------
__global__ void __launch_bounds__(256) rope_kernel(
    const __half* __restrict__ qkv,
    __half* __restrict__ Q, __half* __restrict__ K, __half* __restrict__ V)
{
    int idx = blockIdx.x * blockDim.x + threadIdx.x;
    int d = idx & 31;
    int h = (idx >> 5) & 15;
    int s = (idx >> 9) & 2047;
    int b = idx >> 20;
    int t = b*S_ + s;
    size_t base = (size_t)t*3072 + h*64 + d;
    float q1 = __half2float(qkv[base]);
    float q2 = __half2float(qkv[base + 32]);
    float k1 = __half2float(qkv[base + 1024]);
    float k2 = __half2float(qkv[base + 1056]);
    __half v1 = qkv[base + 2048];
    __half v2 = qkv[base + 2080];
    float inv = powf(10000.0f, -(float)d * (1.0f/32.0f));
    float ang = (float)s * inv;
    float sn, cs;
    sincosf(ang, &sn, &cs);
    size_t o = ((size_t)(b*H_ + h)*S_ + s)*64 + d;
    Q[o]      = __float2half((q1*cs - q2*sn) * 0.125f);
    Q[o + 32] = __float2half((q2*cs + q1*sn) * 0.125f);
    K[o]      = __float2half(k1*cs - k2*sn);
    K[o + 32] = __float2half(k2*cs + k1*sn);
    V[o]      = v1;
    V[o + 32] = v2;
}

// ----------------------------------------------------------------------
// Tensor-core flash attention (validated round 4).
// ----------------------------------------------------------------------
__global__ void __launch_bounds__(256) fattn_kernel(
    const __half* __restrict__ Q, const __half* __restrict__ K,
    const __half* __restrict__ V, const unsigned char* __restrict__ mask,
    __half* __restrict__ O)
{
    __shared__ __half sk[2][64*64];
    __shared__ __half sv[2][64*64];
    __shared__ float  smk[2][64];

    int tid  = threadIdx.x;
    int lane = tid & 31;
    int warp = tid >> 5;
    int bh = blockIdx.y;
    int b  = bh >> 4;
    int h  = bh & 15;
    int qt = blockIdx.x;

    const __half* Qb = Q + ((size_t)bh*S_ + (size_t)qt*128)*64;
    const __half* Kb = K + (size_t)bh*S_*64;
    const __half* Vb = V + (size_t)bh*S_*64;

    uint32_t skA = (uint32_t)__cvta_generic_to_shared(&sk[0][0]);
    uint32_t svA = (uint32_t)__cvta_generic_to_shared(&sv[0][0]);

    #pragma unroll
    for (int i = 0; i < 4; i++) {
        int c = tid + i*256;
        int r = c >> 3;
        int g = c & 7;
        uint32_t off = (uint32_t)(r*64 + ((g ^ (r & 7))*8)) * 2u;
        cpa16(skA + off, Qb + (size_t)r*64 + g*8);
    }
    cpa_commit();
    cpa_wait0();
    __syncthreads();

    uint32_t qf[4][4];
    {
        int row = warp*16 + (lane & 15);
        #pragma unroll
        for (int ks = 0; ks < 4; ks++) {
            int kg = ks*2 + (lane >> 4);
            uint32_t ad = skA + (uint32_t)(row*64 + ((kg ^ (row & 7))*8)) * 2u;
            ldsm4(qf[ks], ad);
        }
    }
    __syncthreads();

    float m1 = -3.0e38f, m2 = -3.0e38f, l1 = 0.f, l2 = 0.f;
    float acc[8][4];
    #pragma unroll
    for (int nt = 0; nt < 8; nt++)
        #pragma unroll
        for (int t = 0; t < 4; t++)
            acc[nt][t] = 0.f;

    {
        int r = tid >> 2;
        #pragma unroll
        for (int j = 0; j < 2; j++) {
            int g = (tid & 3)*2 + j;
            uint32_t off = (uint32_t)(r*64 + ((g ^ (r & 7))*8)) * 2u;
            cpa16(skA + off, Kb + (size_t)r*64 + g*8);
            cpa16(svA + off, Vb + (size_t)r*64 + g*8);
        }
        if (tid < 64)
            smk[0][tid] = mask[(size_t)b*S_ + tid] ? -3.0e38f : 0.0f;
    }
    cpa_commit();

    const int NKT = S_/64;
    for (int kt = 0; kt < NKT; kt++) {
        int buf = kt & 1;
        if (kt + 1 < NKT) {
            int nb = buf ^ 1;
            const __half* Kt = Kb + (size_t)(kt+1)*64*64;
            const __half* Vt = Vb + (size_t)(kt+1)*64*64;
            int r = tid >> 2;
            #pragma unroll
            for (int j = 0; j < 2; j++) {
                int g = (tid & 3)*2 + j;
                uint32_t off = (uint32_t)(nb*8192 + (r*64 + ((g ^ (r & 7))*8))*2);
                cpa16(skA + off, Kt + (size_t)r*64 + g*8);
                cpa16(svA + off, Vt + (size_t)r*64 + g*8);
            }
            if (tid < 64)
                smk[nb][tid] = mask[(size_t)b*S_ + (kt+1)*64 + tid] ? -3.0e38f : 0.0f;
            cpa_commit();
            cpa_wait1();
        } else {
            cpa_wait0();
        }
        __syncthreads();

        float sc[8][4];
        #pragma unroll
        for (int nt = 0; nt < 8; nt++) {
            sc[nt][0] = 0.f; sc[nt][1] = 0.f; sc[nt][2] = 0.f; sc[nt][3] = 0.f;
            int mrow = nt*8 + (lane & 7);
            uint32_t kb0[4], kb1[4];
            {
                int kg = (lane >> 3);
                ldsm4(kb0, skA + (uint32_t)(buf*8192 + (mrow*64 + ((kg ^ (mrow & 7))*8))*2));
            }
            {
                int kg = 4 + (lane >> 3);
                ldsm4(kb1, skA + (uint32_t)(buf*8192 + (mrow*64 + ((kg ^ (mrow & 7))*8))*2));
            }
            mma16816(sc[nt], qf[0], kb0 + 0);
            mma16816(sc[nt], qf[1], kb0 + 2);
            mma16816(sc[nt], qf[2], kb1 + 0);
            mma16816(sc[nt], qf[3], kb1 + 2);
        }

        float rmax1 = -3.0e38f, rmax2 = -3.0e38f;
        #pragma unroll
        for (int nt = 0; nt < 8; nt++) {
            int c0 = nt*8 + (lane & 3)*2;
            float k0 = smk[buf][c0];
            float k1 = smk[buf][c0 + 1];
            sc[nt][0] += k0; sc[nt][1] += k1;
            sc[nt][2] += k0; sc[nt][3] += k1;
            rmax1 = fmaxf(rmax1, fmaxf(sc[nt][0], sc[nt][1]));
            rmax2 = fmaxf(rmax2, fmaxf(sc[nt][2], sc[nt][3]));
        }
        rmax1 = fmaxf(rmax1, __shfl_xor_sync(0xffffffffu, rmax1, 1));
        rmax1 = fmaxf(rmax1, __shfl_xor_sync(0xffffffffu, rmax1, 2));
        rmax2 = fmaxf(rmax2, __shfl_xor_sync(0xffffffffu, rmax2, 1));
        rmax2 = fmaxf(rmax2, __shfl_xor_sync(0xffffffffu, rmax2, 2));

        float mn1 = fmaxf(m1, rmax1);
        float mn2 = fmaxf(m2, rmax2);
        float corr1 = __expf(m1 - mn1);
        float corr2 = __expf(m2 - mn2);
        float rs1 = 0.f, rs2 = 0.f;

        uint32_t pf[4][4];
        #pragma unroll
        for (int ktp = 0; ktp < 4; ktp++) {
            #pragma unroll
            for (int sub = 0; sub < 2; sub++) {
                int nt = ktp*2 + sub;
                float p0 = __expf(sc[nt][0] - mn1);
                float p1 = __expf(sc[nt][1] - mn1);
                float p2 = __expf(sc[nt][2] - mn2);
                float p3 = __expf(sc[nt][3] - mn2);
                rs1 += p0 + p1;
                rs2 += p2 + p3;
                pf[ktp][sub*2 + 0] = h2u(__floats2half2_rn(p0, p1));
                pf[ktp][sub*2 + 1] = h2u(__floats2half2_rn(p2, p3));
            }
        }
        rs1 += __shfl_xor_sync(0xffffffffu, rs1, 1);
        rs1 += __shfl_xor_sync(0xffffffffu, rs1, 2);
        rs2 += __shfl_xor_sync(0xffffffffu, rs2, 1);
        rs2 += __shfl_xor_sync(0xffffffffu, rs2, 2);

        m1 = mn1; m2 = mn2;
        l1 = l1*corr1 + rs1;
        l2 = l2*corr2 + rs2;
        #pragma unroll
        for (int nt = 0; nt < 8; nt++) {
            acc[nt][0] *= corr1; acc[nt][1] *= corr1;
            acc[nt][2] *= corr2; acc[nt][3] *= corr2;
        }

        #pragma unroll
        for (int nt = 0; nt < 8; nt++) {
            #pragma unroll
            for (int ktp = 0; ktp < 4; ktp++) {
                uint32_t vb[2];
                int r = ktp*16 + (lane & 15);
                int g = nt ^ (r & 7);
                ldsm2t(vb, svA + (uint32_t)(buf*8192 + (r*64 + g*8)*2));
                mma16816(acc[nt], pf[ktp], vb);
            }
        }
        __syncthreads();
    }

    float il1 = 1.0f / l1;
    float il2 = 1.0f / l2;
    int r1 = qt*128 + warp*16 + (lane >> 2);
    int r2 = r1 + 8;
    size_t row1 = ((size_t)b*S_ + r1)*DIM_ + h*64;
    size_t row2 = ((size_t)b*S_ + r2)*DIM_ + h*64;
    #pragma unroll
    for (int nt = 0; nt < 8; nt++) {
        int c = nt*8 + (lane & 3)*2;
        *(__half2*)(O + row1 + c) = __floats2half2_rn(acc[nt][0]*il1, acc[nt][1]*il1);
        *(__half2*)(O + row2 + c) = __floats2half2_rn(acc[nt][2]*il2, acc[nt][3]*il2);
    }
}

// ----------------------------------------------------------------------
// Orchestration
// ----------------------------------------------------------------------
extern "C" void kernel_launch(void* const* d_in, const int* in_sizes, int n_in,
                              void* d_out, int out_size)
{
    (void)in_sizes; (void)n_in; (void)out_size;
    const float*         x     = (const float*)d_in[0];
    const unsigned char* mask  = (const unsigned char*)d_in[1];
    const float*         qkv_w = (const float*)d_in[2];
    const float*         qkv_b = (const float*)d_in[3];
    const float*         out_w = (const float*)d_in[4];
    const float*         out_b = (const float*)d_in[5];
    const float*         ln1_g = (const float*)d_in[6];
    const float*         ln1_b = (const float*)d_in[7];
    const float*         ln2_g = (const float*)d_in[8];
    const float*         ln2_b = (const float*)d_in[9];
    const float*         w1    = (const float*)d_in[10];
    const float*         b1    = (const float*)d_in[11];
    const float*         w2    = (const float*)d_in[12];
    const float*         b2    = (const float*)d_in[13];
    float* out = (float*)d_out;

    __half* h16;
    __half* qkv16;
    __half* q16;
    __half* k16;
    __half* v16;
    __half* ctx16;
    __half* mid16;
    __half* qkvw16;
    __half* outw16;
    __half* w116;
    __half* w216;
    float* x1;
    cudaGetSymbolAddress((void**)&h16,    g_h16);
    cudaGetSymbolAddress((void**)&qkv16,  g_qkv16);
    cudaGetSymbolAddress((void**)&q16,    g_q16);
    cudaGetSymbolAddress((void**)&k16,    g_k16);
    cudaGetSymbolAddress((void**)&v16,    g_v16);
    cudaGetSymbolAddress((void**)&ctx16,  g_ctx16);
    cudaGetSymbolAddress((void**)&x1,     g_x1);
    cudaGetSymbolAddress((void**)&mid16,  g_mid16);
    cudaGetSymbolAddress((void**)&qkvw16, g_qkvw16);
    cudaGetSymbolAddress((void**)&outw16, g_outw16);
    cudaGetSymbolAddress((void**)&w116,   g_w116);
    cudaGetSymbolAddress((void**)&w216,   g_w216);

    f2h_kernel<<<DIM_*3*DIM_/4/1024, 256>>>((const float4*)qkv_w, (__half2*)qkvw16, DIM_*3*DIM_/4);
    f2h_kernel<<<DIM_*DIM_/4/1024,   256>>>((const float4*)out_w, (__half2*)outw16, DIM_*DIM_/4);
    f2h_kernel<<<DIM_*FFN_/4/1024,   256>>>((const float4*)w1,    (__half2*)w116,   DIM_*FFN_/4);
    f2h_kernel<<<FFN_*DIM_/4/1024,   256>>>((const float4*)w2,    (__half2*)w216,   FFN_*DIM_/4);

    ln_kernel<<<NTOK, 256>>>(x, ln1_g, ln1_b, h16);

    hgemm_kernel<0, 0, 1><<<dim3(3*DIM_/BN, NTOK/BM), 256>>>(
        h16, qkvw16, qkv_b, (const float*)0, (void*)qkv16, NTOK, 3*DIM_, DIM_);

    rope_kernel<<<(NTOK*H_*32)/256, 256>>>(qkv16, q16, k16, v16);

    fattn_kernel<<<dim3(S_/128, B_*H_), 256>>>(q16, k16, v16, mask, ctx16);

    hgemm_kernel<0, 1, 0><<<dim3(DIM_/BN, NTOK/BM), 256>>>(
        ctx16, outw16, out_b, x, (void*)x1, NTOK, DIM_, DIM_);

    ln_kernel<<<NTOK, 256>>>(x1, ln2_g, ln2_b, h16);

    hgemm_kernel<1, 0, 1><<<dim3(FFN_/BN, NTOK/BM), 256>>>(
        h16, w116, b1, (const float*)0, (void*)mid16, NTOK, FFN_, DIM_);

    hgemm_kernel<0, 1, 0><<<dim3(DIM_/BN, NTOK/BM), 256>>>(
        mid16, w216, b2, x1, (void*)out, NTOK, DIM_, FFN_);
}